// round 1
// baseline (speedup 1.0000x reference)
#include <cuda_runtime.h>
#include <math.h>

#define T_TOK 512
#define DM    512
#define DE    1024
#define NE    64
#define NPAIR 1024
#define WS    66   // smem row stride (floats) for weight tiles: even (8B-aligned LDS.64), 2-way bank conflict only

// ---------------- scratch (static device globals; no allocation) ----------------
__device__ float g_probs[T_TOK * NE];      // softmax probs per token (for aux loss)
__device__ int   g_topidx[NPAIR];          // flat assignment a[2t+k] = expert
__device__ float g_topw[NPAIR];            // combine weight per assignment
__device__ int   g_rowTok[NPAIR];          // per compacted row: flat assignment index (t = v>>1)
__device__ float g_rowW[NPAIR];            // per compacted row: combine weight
__device__ int   g_cnt[NE];
__device__ int   g_off[NE];
__device__ float g_h[(size_t)NPAIR * DE];  // silu(gate)*up, [row][F], 4 MB

// ---------------- packed f32x2 FMA ----------------
__device__ __forceinline__ unsigned long long ffma2(unsigned long long a,
                                                    unsigned long long b,
                                                    unsigned long long c) {
    unsigned long long d;
    asm("fma.rn.f32x2 %0, %1, %2, %3;" : "=l"(d) : "l"(a), "l"(b), "l"(c));
    return d;
}
__device__ __forceinline__ float f2_lo(unsigned long long v) { return __uint_as_float((unsigned)v); }
__device__ __forceinline__ float f2_hi(unsigned long long v) { return __uint_as_float((unsigned)(v >> 32)); }
__device__ __forceinline__ float f2_sum(unsigned long long v) { return f2_lo(v) + f2_hi(v); }

// ---------------- kernel 1: router (4 tokens per block) ----------------
__global__ __launch_bounds__(256) void router_kernel(const float* __restrict__ x,
                                                     const float* __restrict__ rw) {
    __shared__ float xs[4 * DM];
    __shared__ float lg[4 * NE];
    int tid = threadIdx.x, lane = tid & 31, warp = tid >> 5;
    int tbase = blockIdx.x * 4;

    for (int i = tid; i < 4 * DM / 4; i += 256)
        *(float4*)(xs + i * 4) = *(const float4*)(x + (size_t)tbase * DM + i * 4);
    __syncthreads();

    // each warp computes 8 experts' logits for the 4 tokens
    for (int j = 0; j < 8; j++) {
        int e = warp * 8 + j;
        const float* w = rw + (size_t)e * DM;
        float acc[4] = {0.f, 0.f, 0.f, 0.f};
        #pragma unroll
        for (int q = 0; q < 4; q++) {
            float4 wv = *(const float4*)(w + (size_t)(lane + 32 * q) * 4);
            int kb = (lane + 32 * q) * 4;
            #pragma unroll
            for (int t = 0; t < 4; t++) {
                acc[t] += wv.x * xs[t * DM + kb + 0];
                acc[t] += wv.y * xs[t * DM + kb + 1];
                acc[t] += wv.z * xs[t * DM + kb + 2];
                acc[t] += wv.w * xs[t * DM + kb + 3];
            }
        }
        #pragma unroll
        for (int t = 0; t < 4; t++) {
            float a = acc[t];
            #pragma unroll
            for (int off = 16; off; off >>= 1) a += __shfl_xor_sync(0xffffffffu, a, off);
            if (lane == 0) lg[t * NE + e] = a;
        }
    }
    __syncthreads();

    // warps 0..3: per-token epilogue (softmax probs + top-2)
    if (warp < 4) {
        int tl = warp;
        int t = tbase + tl;
        float l0 = lg[tl * NE + lane];
        float l1 = lg[tl * NE + lane + 32];
        // full softmax for aux
        float m = fmaxf(l0, l1);
        #pragma unroll
        for (int off = 16; off; off >>= 1) m = fmaxf(m, __shfl_xor_sync(0xffffffffu, m, off));
        float p0 = expf(l0 - m), p1 = expf(l1 - m);
        float s = p0 + p1;
        #pragma unroll
        for (int off = 16; off; off >>= 1) s += __shfl_xor_sync(0xffffffffu, s, off);
        g_probs[(size_t)t * NE + lane]      = p0 / s;
        g_probs[(size_t)t * NE + lane + 32] = p1 / s;
        // top-1 (ties -> lower index, matching lax.top_k)
        float v; int ix;
        if (l1 > l0) { v = l1; ix = lane + 32; } else { v = l0; ix = lane; }
        #pragma unroll
        for (int off = 16; off; off >>= 1) {
            float ov = __shfl_xor_sync(0xffffffffu, v, off);
            int   oi = __shfl_xor_sync(0xffffffffu, ix, off);
            if (ov > v || (ov == v && oi < ix)) { v = ov; ix = oi; }
        }
        float v1 = v; int i1 = ix;
        // top-2: exclude i1
        float c0 = (lane == i1)      ? -INFINITY : l0;
        float c1 = (lane + 32 == i1) ? -INFINITY : l1;
        if (c1 > c0) { v = c1; ix = lane + 32; } else { v = c0; ix = lane; }
        #pragma unroll
        for (int off = 16; off; off >>= 1) {
            float ov = __shfl_xor_sync(0xffffffffu, v, off);
            int   oi = __shfl_xor_sync(0xffffffffu, ix, off);
            if (ov > v || (ov == v && oi < ix)) { v = ov; ix = oi; }
        }
        float v2 = v; int i2 = ix;
        if (lane == 0) {
            float q = expf(v2 - v1);            // <= 1, stable
            float wA = 1.f / (1.f + q);
            float wB = q / (1.f + q);
            g_topidx[2 * t]     = i1;
            g_topidx[2 * t + 1] = i2;
            g_topw[2 * t]       = wA;
            g_topw[2 * t + 1]   = wB;
        }
    }
}

// ---------------- kernel 2: deterministic grouping (1 block) ----------------
__global__ __launch_bounds__(1024) void group_kernel() {
    __shared__ int cnt_s[NE], off_s[NE];
    int tid = threadIdx.x, lane = tid & 31, warp = tid >> 5;

    for (int e = warp; e < NE; e += 32) {
        int c = 0;
        for (int ch = 0; ch < NPAIR / 32; ch++) {
            int a = g_topidx[ch * 32 + lane];
            unsigned mask = __ballot_sync(0xffffffffu, a == e);
            c += __popc(mask);
        }
        if (lane == 0) cnt_s[e] = c;
    }
    __syncthreads();
    if (tid == 0) {
        int r = 0;
        for (int e = 0; e < NE; e++) { off_s[e] = r; r += cnt_s[e]; }
    }
    __syncthreads();
    for (int e = warp; e < NE; e += 32) {
        int pos = off_s[e];
        for (int ch = 0; ch < NPAIR / 32; ch++) {
            int idx = ch * 32 + lane;
            int a = g_topidx[idx];
            unsigned mask = __ballot_sync(0xffffffffu, a == e);
            if (a == e) {
                int r = pos + __popc(mask & ((1u << lane) - 1u));
                g_rowTok[r] = idx;
                g_rowW[r]   = g_topw[idx];
            }
            pos += __popc(mask);
        }
    }
    if (tid < NE) { g_cnt[tid] = cnt_s[tid]; g_off[tid] = off_s[tid]; }
}

// ---------------- kernel 3: aux loss ----------------
__global__ __launch_bounds__(1024) void aux_kernel(float* auxp) {
    __shared__ float part[1024];
    int tid = threadIdx.x;
    int e = tid & 63, c = tid >> 6;          // 16 chunks of 32 tokens
    float s = 0.f;
    int t0 = c * 32;
    for (int t = t0; t < t0 + 32; t++) s += g_probs[(size_t)t * NE + e];
    part[tid] = s;
    __syncthreads();
    if (tid < NE) {
        float tot = 0.f;
        for (int j = 0; j < 16; j++) tot += part[e + j * 64];
        part[tid] = tot * (64.0f / 512.0f);  // mean_e * E
    }
    __syncthreads();
    if (tid == 0 && auxp) {
        float m = 0.f;
        for (int i = 0; i < NE; i++) m += part[i];
        m *= (1.0f / 64.0f);
        float v = 0.f;
        for (int i = 0; i < NE; i++) { float d = part[i] - m; v += d * d; }
        auxp[0] = v * (1.0f / 63.0f);        // unbiased var
    }
}

// ---------------- kernel 4: gate/up grouped GEMM -> h = silu(g)*u ----------------
// grid (8, 64): (f-tile of 128, expert). 256 thr = 32 f-threads x 8 token-threads.
// per thread: 2 tokens x 4 f x {gate,up} f32x2 accumulators.
__global__ __launch_bounds__(256) void gateup_kernel(const float* __restrict__ x,
                                                     const float* __restrict__ wg,
                                                     const float* __restrict__ wu) {
    int e = blockIdx.y;
    int n = g_cnt[e];
    if (n == 0) return;
    int base = g_off[e];
    int ft = blockIdx.x * 128;

    extern __shared__ float sm[];
    float* xs = sm;                    // 16 x 512
    float* gs = sm + 16 * DM;          // 128 x WS
    float* us = gs + 128 * WS;         // 128 x WS

    int tid = threadIdx.x, tf = tid & 31, tt = tid >> 5;
    const float* wgE = wg + ((size_t)e * DE + ft) * DM;
    const float* wuE = wu + ((size_t)e * DE + ft) * DM;

    for (int t0 = 0; t0 < n; t0 += 16) {
        __syncthreads();  // guard xs reuse from previous chunk's compute
        // load 16 token rows of x (dummy rows replicate row 0)
        for (int idx = tid; idx < 16 * 128; idx += 256) {
            int r = idx >> 7, c = idx & 127;
            int rr = (t0 + r < n) ? r : 0;
            int t = g_rowTok[base + t0 + rr] >> 1;
            *(float4*)(xs + r * DM + c * 4) = *(const float4*)(x + (size_t)t * DM + c * 4);
        }

        unsigned long long ag[2][4], au[2][4];
        #pragma unroll
        for (int t = 0; t < 2; t++)
            #pragma unroll
            for (int i = 0; i < 4; i++) { ag[t][i] = 0ull; au[t][i] = 0ull; }

        for (int k0 = 0; k0 < DM; k0 += 64) {
            __syncthreads();  // xs visible (1st iter) / weight tiles free (later iters)
            for (int idx = tid; idx < 2048; idx += 256) {
                int r = idx >> 4, c = (idx & 15) * 4;
                float4 vg = *(const float4*)(wgE + (size_t)r * DM + k0 + c);
                float4 vu = *(const float4*)(wuE + (size_t)r * DM + k0 + c);
                float* dg = gs + r * WS + c;
                dg[0] = vg.x; dg[1] = vg.y; dg[2] = vg.z; dg[3] = vg.w;
                float* du = us + r * WS + c;
                du[0] = vu.x; du[1] = vu.y; du[2] = vu.z; du[3] = vu.w;
            }
            __syncthreads();
            #pragma unroll
            for (int kp = 0; kp < 32; kp++) {
                int kk = kp * 2;
                unsigned long long x0 = *(unsigned long long*)(xs + (tt * 2 + 0) * DM + k0 + kk);
                unsigned long long x1 = *(unsigned long long*)(xs + (tt * 2 + 1) * DM + k0 + kk);
                #pragma unroll
                for (int i = 0; i < 4; i++) {
                    unsigned long long wgv = *(unsigned long long*)(gs + (tf + 32 * i) * WS + kk);
                    unsigned long long wuv = *(unsigned long long*)(us + (tf + 32 * i) * WS + kk);
                    ag[0][i] = ffma2(wgv, x0, ag[0][i]);
                    ag[1][i] = ffma2(wgv, x1, ag[1][i]);
                    au[0][i] = ffma2(wuv, x0, au[0][i]);
                    au[1][i] = ffma2(wuv, x1, au[1][i]);
                }
            }
        }
        // epilogue: h = silu(g) * u, coalesced across tf
        #pragma unroll
        for (int tl = 0; tl < 2; tl++) {
            int trow = t0 + tt * 2 + tl;
            if (trow < n) {
                int row = base + trow;
                #pragma unroll
                for (int i = 0; i < 4; i++) {
                    float g = f2_sum(ag[tl][i]);
                    float u = f2_sum(au[tl][i]);
                    float hv = (g / (1.f + expf(-g))) * u;
                    g_h[(size_t)row * DE + ft + tf + 32 * i] = hv;
                }
            }
        }
    }
}

// ---------------- kernel 5: down grouped GEMM + weighted scatter ----------------
// grid (4, 64): (d-tile of 128, expert). out += topw * (h @ w_down^T)
__global__ __launch_bounds__(256) void down_kernel(const float* __restrict__ wd,
                                                   float* __restrict__ out) {
    int e = blockIdx.y;
    int n = g_cnt[e];
    if (n == 0) return;
    int base = g_off[e];
    int dt = blockIdx.x * 128;

    extern __shared__ float sm[];
    float* hs = sm;                    // 16 x 1024
    float* ws = sm + 16 * DE;          // 128 x WS

    int tid = threadIdx.x, tf = tid & 31, tt = tid >> 5;
    const float* wdE = wd + ((size_t)e * DM + dt) * DE;

    for (int t0 = 0; t0 < n; t0 += 16) {
        __syncthreads();
        for (int idx = tid; idx < 16 * 256; idx += 256) {
            int r = idx >> 8, c = idx & 255;
            int rr = (t0 + r < n) ? r : 0;
            int row = base + t0 + rr;
            *(float4*)(hs + r * DE + c * 4) = *(const float4*)(g_h + (size_t)row * DE + c * 4);
        }

        unsigned long long acc[2][4];
        #pragma unroll
        for (int t = 0; t < 2; t++)
            #pragma unroll
            for (int i = 0; i < 4; i++) acc[t][i] = 0ull;

        for (int k0 = 0; k0 < DE; k0 += 64) {
            __syncthreads();
            for (int idx = tid; idx < 2048; idx += 256) {
                int r = idx >> 4, c = (idx & 15) * 4;
                float4 v = *(const float4*)(wdE + (size_t)r * DE + k0 + c);
                float* dw = ws + r * WS + c;
                dw[0] = v.x; dw[1] = v.y; dw[2] = v.z; dw[3] = v.w;
            }
            __syncthreads();
            #pragma unroll
            for (int kp = 0; kp < 32; kp++) {
                int kk = kp * 2;
                unsigned long long h0 = *(unsigned long long*)(hs + (tt * 2 + 0) * DE + k0 + kk);
                unsigned long long h1 = *(unsigned long long*)(hs + (tt * 2 + 1) * DE + k0 + kk);
                #pragma unroll
                for (int i = 0; i < 4; i++) {
                    unsigned long long w = *(unsigned long long*)(ws + (tf + 32 * i) * WS + kk);
                    acc[0][i] = ffma2(w, h0, acc[0][i]);
                    acc[1][i] = ffma2(w, h1, acc[1][i]);
                }
            }
        }
        #pragma unroll
        for (int tl = 0; tl < 2; tl++) {
            int trow = t0 + tt * 2 + tl;
            if (trow < n) {
                int fidx = g_rowTok[base + trow];
                int t = fidx >> 1;
                float wt = g_rowW[base + trow];
                #pragma unroll
                for (int i = 0; i < 4; i++) {
                    float y = f2_sum(acc[tl][i]);
                    atomicAdd(out + (size_t)t * DM + dt + tf + 32 * i, wt * y);
                }
            }
        }
    }
}

// ---------------- launch ----------------
extern "C" void kernel_launch(void* const* d_in, const int* in_sizes, int n_in,
                              void* d_out, int out_size) {
    const float* x  = (const float*)d_in[0];
    const float* rw = (const float*)d_in[1];
    const float* wg = (const float*)d_in[2];
    const float* wu = (const float*)d_in[3];
    const float* wd = (const float*)d_in[4];
    float* out = (float*)d_out;

    cudaMemsetAsync(d_out, 0, (size_t)out_size * sizeof(float), 0);

    router_kernel<<<T_TOK / 4, 256>>>(x, rw);
    group_kernel<<<1, 1024>>>();

    float* auxp = (out_size > T_TOK * DM) ? out + (size_t)T_TOK * DM : nullptr;
    aux_kernel<<<1, 1024>>>(auxp);

    int smem2 = (16 * DM + 2 * 128 * WS) * (int)sizeof(float);   // 100,352 B
    cudaFuncSetAttribute(gateup_kernel, cudaFuncAttributeMaxDynamicSharedMemorySize, smem2);
    gateup_kernel<<<dim3(8, 64), 256, smem2>>>(x, wg, wu);

    int smem3 = (16 * DE + 128 * WS) * (int)sizeof(float);       // 99,328 B
    cudaFuncSetAttribute(down_kernel, cudaFuncAttributeMaxDynamicSharedMemorySize, smem3);
    down_kernel<<<dim3(4, 64), 256, smem3>>>(wd, out);
}

// round 2
// speedup vs baseline: 1.3104x; 1.3104x over previous
#include <cuda_runtime.h>
#include <math.h>

#define T_TOK 512
#define DM    512
#define DE    1024
#define NE    64
#define NPAIR 1024

// ---------------- scratch (static device globals; no allocation) ----------------
__device__ float g_probs[T_TOK * NE];
__device__ int   g_topidx[NPAIR];
__device__ float g_topw[NPAIR];
__device__ int   g_rowTok[NPAIR];
__device__ float g_rowW[NPAIR];
__device__ int   g_cnt[NE];
__device__ int   g_off[NE];
__device__ float g_h[(size_t)NPAIR * DE];   // silu(gate)*up, [row][F], 4 MB

// ---------------- packed f32x2 FMA ----------------
__device__ __forceinline__ unsigned long long ffma2(unsigned long long a,
                                                    unsigned long long b,
                                                    unsigned long long c) {
    unsigned long long d;
    asm("fma.rn.f32x2 %0, %1, %2, %3;" : "=l"(d) : "l"(a), "l"(b), "l"(c));
    return d;
}
__device__ __forceinline__ float f2_sum(unsigned long long v) {
    return __uint_as_float((unsigned)v) + __uint_as_float((unsigned)(v >> 32));
}

__device__ __forceinline__ void cpa16(const void* smem_dst, const void* gsrc) {
    unsigned a = (unsigned)__cvta_generic_to_shared(smem_dst);
    asm volatile("cp.async.cg.shared.global [%0], [%1], 16;" :: "r"(a), "l"(gsrc));
}
__device__ __forceinline__ void cpa_commit() {
    asm volatile("cp.async.commit_group;" ::: "memory");
}
__device__ __forceinline__ void cpa_wait0() {
    asm volatile("cp.async.wait_group 0;" ::: "memory");
}

// ---------------- kernel 1: router (4 tokens per block) ----------------
__global__ __launch_bounds__(256) void router_kernel(const float* __restrict__ x,
                                                     const float* __restrict__ rw) {
    __shared__ float xs[4 * DM];
    __shared__ float lg[4 * NE];
    int tid = threadIdx.x, lane = tid & 31, warp = tid >> 5;
    int tbase = blockIdx.x * 4;

    for (int i = tid; i < 4 * DM / 4; i += 256)
        *(float4*)(xs + i * 4) = *(const float4*)(x + (size_t)tbase * DM + i * 4);
    __syncthreads();

    for (int j = 0; j < 8; j++) {
        int e = warp * 8 + j;
        const float* w = rw + (size_t)e * DM;
        float acc[4] = {0.f, 0.f, 0.f, 0.f};
        #pragma unroll
        for (int q = 0; q < 4; q++) {
            float4 wv = *(const float4*)(w + (size_t)(lane + 32 * q) * 4);
            int kb = (lane + 32 * q) * 4;
            #pragma unroll
            for (int t = 0; t < 4; t++) {
                acc[t] += wv.x * xs[t * DM + kb + 0];
                acc[t] += wv.y * xs[t * DM + kb + 1];
                acc[t] += wv.z * xs[t * DM + kb + 2];
                acc[t] += wv.w * xs[t * DM + kb + 3];
            }
        }
        #pragma unroll
        for (int t = 0; t < 4; t++) {
            float a = acc[t];
            #pragma unroll
            for (int off = 16; off; off >>= 1) a += __shfl_xor_sync(0xffffffffu, a, off);
            if (lane == 0) lg[t * NE + e] = a;
        }
    }
    __syncthreads();

    if (warp < 4) {
        int tl = warp;
        int t = tbase + tl;
        float l0 = lg[tl * NE + lane];
        float l1 = lg[tl * NE + lane + 32];
        float m = fmaxf(l0, l1);
        #pragma unroll
        for (int off = 16; off; off >>= 1) m = fmaxf(m, __shfl_xor_sync(0xffffffffu, m, off));
        float p0 = expf(l0 - m), p1 = expf(l1 - m);
        float s = p0 + p1;
        #pragma unroll
        for (int off = 16; off; off >>= 1) s += __shfl_xor_sync(0xffffffffu, s, off);
        g_probs[(size_t)t * NE + lane]      = p0 / s;
        g_probs[(size_t)t * NE + lane + 32] = p1 / s;

        float v; int ix;
        if (l1 > l0) { v = l1; ix = lane + 32; } else { v = l0; ix = lane; }
        #pragma unroll
        for (int off = 16; off; off >>= 1) {
            float ov = __shfl_xor_sync(0xffffffffu, v, off);
            int   oi = __shfl_xor_sync(0xffffffffu, ix, off);
            if (ov > v || (ov == v && oi < ix)) { v = ov; ix = oi; }
        }
        float v1 = v; int i1 = ix;
        float c0 = (lane == i1)      ? -INFINITY : l0;
        float c1 = (lane + 32 == i1) ? -INFINITY : l1;
        if (c1 > c0) { v = c1; ix = lane + 32; } else { v = c0; ix = lane; }
        #pragma unroll
        for (int off = 16; off; off >>= 1) {
            float ov = __shfl_xor_sync(0xffffffffu, v, off);
            int   oi = __shfl_xor_sync(0xffffffffu, ix, off);
            if (ov > v || (ov == v && oi < ix)) { v = ov; ix = oi; }
        }
        float v2 = v; int i2 = ix;
        if (lane == 0) {
            float q = expf(v2 - v1);
            g_topidx[2 * t]     = i1;
            g_topidx[2 * t + 1] = i2;
            g_topw[2 * t]       = 1.f / (1.f + q);
            g_topw[2 * t + 1]   = q / (1.f + q);
        }
    }
}

// ---------------- kernel 2: deterministic grouping (1 block) ----------------
__global__ __launch_bounds__(1024) void group_kernel() {
    __shared__ int cnt_s[NE], off_s[NE];
    int tid = threadIdx.x, lane = tid & 31, warp = tid >> 5;

    for (int e = warp; e < NE; e += 32) {
        int c = 0;
        for (int ch = 0; ch < NPAIR / 32; ch++) {
            int a = g_topidx[ch * 32 + lane];
            unsigned mask = __ballot_sync(0xffffffffu, a == e);
            c += __popc(mask);
        }
        if (lane == 0) cnt_s[e] = c;
    }
    __syncthreads();
    if (tid == 0) {
        int r = 0;
        for (int e = 0; e < NE; e++) { off_s[e] = r; r += cnt_s[e]; }
    }
    __syncthreads();
    for (int e = warp; e < NE; e += 32) {
        int pos = off_s[e];
        for (int ch = 0; ch < NPAIR / 32; ch++) {
            int idx = ch * 32 + lane;
            int a = g_topidx[idx];
            unsigned mask = __ballot_sync(0xffffffffu, a == e);
            if (a == e) {
                int r = pos + __popc(mask & ((1u << lane) - 1u));
                g_rowTok[r] = idx;
                g_rowW[r]   = g_topw[idx];
            }
            pos += __popc(mask);
        }
    }
    if (tid < NE) { g_cnt[tid] = cnt_s[tid]; g_off[tid] = off_s[tid]; }
}

// ---------------- kernel 3: aux loss ----------------
__global__ __launch_bounds__(1024) void aux_kernel(float* auxp) {
    __shared__ float part[1024];
    int tid = threadIdx.x;
    int e = tid & 63, c = tid >> 6;
    float s = 0.f;
    int t0 = c * 32;
    for (int t = t0; t < t0 + 32; t++) s += g_probs[(size_t)t * NE + e];
    part[tid] = s;
    __syncthreads();
    if (tid < NE) {
        float tot = 0.f;
        for (int j = 0; j < 16; j++) tot += part[e + j * 64];
        part[tid] = tot * (64.0f / 512.0f);
    }
    __syncthreads();
    if (tid == 0 && auxp) {
        float m = 0.f;
        for (int i = 0; i < NE; i++) m += part[i];
        m *= (1.0f / 64.0f);
        float v = 0.f;
        for (int i = 0; i < NE; i++) { float d = part[i] - m; v += d * d; }
        auxp[0] = v * (1.0f / 63.0f);
    }
}

// ---------------- kernel 4: gate/up grouped GEMM -> h = silu(g)*u ----------------
// grid (8 ftile, 64 expert), 256 thr. Lane layout: t = lane&15 (token),
// fi = lane>>4; thread owns (1 token) x (8 f rows) x {gate,up}.
// Weight smem reads are 2-distinct-address broadcasts (near-free crossbar).
// cp.async double-buffered k-chunks of 16.
#define GU_KC 16
#define GU_ST (DM / GU_KC)   // 32 stages
__global__ __launch_bounds__(256) void gateup_kernel(const float* __restrict__ x,
                                                     const float* __restrict__ wg,
                                                     const float* __restrict__ wu) {
    int e = blockIdx.y;
    int n = g_cnt[e];
    if (n == 0) return;
    int base = g_off[e];
    int ft = blockIdx.x * 128;

    __shared__ __align__(16) float xs[2][16][20];
    __shared__ __align__(16) float ws[2][2][128][20];
    __shared__ int tok_s[16];

    int tid = threadIdx.x, lane = tid & 31, warp = tid >> 5;
    int t = lane & 15, fi = lane >> 4;
    int fl = warp * 16 + fi * 8;

    const float* wmat0 = wg + ((size_t)e * DE + ft) * DM;
    const float* wmat1 = wu + ((size_t)e * DE + ft) * DM;

    // per-thread fixed load assignment
    int wp_mat[4], wp_r[4], wp_c[4];
    #pragma unroll
    for (int i = 0; i < 4; i++) {
        int p = i * 256 + tid;
        wp_mat[i] = p >> 9;
        wp_r[i]   = (p >> 2) & 127;
        wp_c[i]   = (p & 3) * 4;
    }
    int xr_ = tid >> 2, xc_ = (tid & 3) * 4;   // tid<64 loads x

    for (int t0 = 0; t0 < n; t0 += 16) {
        __syncthreads();
        if (tid < 16) {
            int rr = min(tid, n - 1 - t0);
            tok_s[tid] = g_rowTok[base + t0 + rr] >> 1;
        }
        __syncthreads();
        const float* myX = (tid < 64) ? (x + (size_t)tok_s[xr_] * DM + xc_) : x;

        unsigned long long ag[8], au[8];
        #pragma unroll
        for (int j = 0; j < 8; j++) { ag[j] = 0ull; au[j] = 0ull; }

        auto loadStage = [&](int s, int bb) {
            int k0 = s * GU_KC;
            #pragma unroll
            for (int i = 0; i < 4; i++) {
                const float* src = (wp_mat[i] ? wmat1 : wmat0) + (size_t)wp_r[i] * DM + k0 + wp_c[i];
                cpa16(&ws[bb][wp_mat[i]][wp_r[i]][wp_c[i]], src);
            }
            if (tid < 64) cpa16(&xs[bb][xr_][xc_], myX + k0);
            cpa_commit();
        };

        loadStage(0, 0);
        for (int s = 0; s < GU_ST; s++) {
            cpa_wait0();
            __syncthreads();
            if (s + 1 < GU_ST) loadStage(s + 1, (s + 1) & 1);
            int bb = s & 1;
            const float* xr = xs[bb][t];
            #pragma unroll
            for (int q = 0; q < 4; q++) {
                unsigned long long x0 = *(const unsigned long long*)(xr + 4 * q);
                unsigned long long x1 = *(const unsigned long long*)(xr + 4 * q + 2);
                #pragma unroll
                for (int j = 0; j < 8; j++) {
                    ulonglong2 w2g = *(const ulonglong2*)(&ws[bb][0][fl + j][4 * q]);
                    ag[j] = ffma2(w2g.x, x0, ag[j]);
                    ag[j] = ffma2(w2g.y, x1, ag[j]);
                    ulonglong2 w2u = *(const ulonglong2*)(&ws[bb][1][fl + j][4 * q]);
                    au[j] = ffma2(w2u.x, x0, au[j]);
                    au[j] = ffma2(w2u.y, x1, au[j]);
                }
            }
        }

        if (t0 + t < n) {
            int row = base + t0 + t;
            float* hp = g_h + (size_t)row * DE + ft + fl;
            #pragma unroll
            for (int j = 0; j < 8; j++) {
                float g = f2_sum(ag[j]);
                float u = f2_sum(au[j]);
                hp[j] = (g / (1.f + expf(-g))) * u;
            }
        }
    }
}

// ---------------- kernel 5: down grouped GEMM + weighted scatter ----------------
// grid (4 dtile, 64 expert). Same lane layout; k over DE in chunks of 32.
#define DN_KC 32
#define DN_ST (DE / DN_KC)   // 32 stages
__global__ __launch_bounds__(256) void down_kernel(const float* __restrict__ wd,
                                                   float* __restrict__ out) {
    int e = blockIdx.y;
    int n = g_cnt[e];
    if (n == 0) return;
    int base = g_off[e];
    int dt = blockIdx.x * 128;

    __shared__ __align__(16) float hs2[2][16][36];
    __shared__ __align__(16) float ws2[2][128][36];
    __shared__ int row_s[16];

    int tid = threadIdx.x, lane = tid & 31, warp = tid >> 5;
    int t = lane & 15, fi = lane >> 4;
    int dl = warp * 16 + fi * 8;

    const float* wdE = wd + ((size_t)e * DM + dt) * DE;

    int wp_r[4], wp_c[4];
    #pragma unroll
    for (int i = 0; i < 4; i++) {
        int p = i * 256 + tid;
        wp_r[i] = p >> 3;
        wp_c[i] = (p & 7) * 4;
    }
    int hr_ = tid >> 3, hc_ = (tid & 7) * 4;   // tid<128 loads h

    for (int t0 = 0; t0 < n; t0 += 16) {
        __syncthreads();
        if (tid < 16) {
            int rr = min(tid, n - 1 - t0);
            row_s[tid] = base + t0 + rr;
        }
        __syncthreads();
        const float* myH = (tid < 128) ? (g_h + (size_t)row_s[hr_] * DE + hc_) : g_h;

        unsigned long long acc[8];
        #pragma unroll
        for (int j = 0; j < 8; j++) acc[j] = 0ull;

        auto loadStage = [&](int s, int bb) {
            int k0 = s * DN_KC;
            #pragma unroll
            for (int i = 0; i < 4; i++)
                cpa16(&ws2[bb][wp_r[i]][wp_c[i]], wdE + (size_t)wp_r[i] * DE + k0 + wp_c[i]);
            if (tid < 128) cpa16(&hs2[bb][hr_][hc_], myH + k0);
            cpa_commit();
        };

        loadStage(0, 0);
        for (int s = 0; s < DN_ST; s++) {
            cpa_wait0();
            __syncthreads();
            if (s + 1 < DN_ST) loadStage(s + 1, (s + 1) & 1);
            int bb = s & 1;
            const float* hr = hs2[bb][t];
            #pragma unroll
            for (int q = 0; q < 8; q++) {
                unsigned long long h0 = *(const unsigned long long*)(hr + 4 * q);
                unsigned long long h1 = *(const unsigned long long*)(hr + 4 * q + 2);
                #pragma unroll
                for (int j = 0; j < 8; j++) {
                    ulonglong2 w2 = *(const ulonglong2*)(&ws2[bb][dl + j][4 * q]);
                    acc[j] = ffma2(w2.x, h0, acc[j]);
                    acc[j] = ffma2(w2.y, h1, acc[j]);
                }
            }
        }

        if (t0 + t < n) {
            int fidx = g_rowTok[base + t0 + t];
            int tok = fidx >> 1;
            float wt = g_rowW[base + t0 + t];
            float* op = out + (size_t)tok * DM + dt + dl;
            #pragma unroll
            for (int j = 0; j < 8; j++)
                atomicAdd(op + j, wt * f2_sum(acc[j]));
        }
    }
}

// ---------------- launch ----------------
extern "C" void kernel_launch(void* const* d_in, const int* in_sizes, int n_in,
                              void* d_out, int out_size) {
    const float* x  = (const float*)d_in[0];
    const float* rw = (const float*)d_in[1];
    const float* wg = (const float*)d_in[2];
    const float* wu = (const float*)d_in[3];
    const float* wd = (const float*)d_in[4];
    float* out = (float*)d_out;

    cudaMemsetAsync(d_out, 0, (size_t)out_size * sizeof(float), 0);

    router_kernel<<<T_TOK / 4, 256>>>(x, rw);
    group_kernel<<<1, 1024>>>();

    float* auxp = (out_size > T_TOK * DM) ? out + (size_t)T_TOK * DM : nullptr;
    aux_kernel<<<1, 1024>>>(auxp);

    gateup_kernel<<<dim3(8, 64), 256>>>(x, wg, wu);
    down_kernel<<<dim3(4, 64), 256>>>(wd, out);
}

// round 3
// speedup vs baseline: 2.0892x; 1.5943x over previous
#include <cuda_runtime.h>
#include <math.h>

#define T_TOK 512
#define DM    512
#define DE    1024
#define NE    64
#define NPAIR 1024
#define CHMAX 128

// ---------------- scratch (static device globals; no allocation) ----------------
__device__ float g_probs[T_TOK * NE];
__device__ int   g_topidx[NPAIR];
__device__ float g_topw[NPAIR];
__device__ int   g_rowTok[NPAIR];
__device__ float g_rowW[NPAIR];
__device__ int   g_cnt[NE];
__device__ int   g_off[NE];
__device__ int   g_chunkE[CHMAX], g_chunkB[CHMAX], g_chunkN[CHMAX];
__device__ int   g_nch;
__device__ float g_h[(size_t)NPAIR * DE];   // silu(gate)*up, [row][F], 4 MB

// ---------------- packed f32x2 FMA ----------------
__device__ __forceinline__ unsigned long long ffma2(unsigned long long a,
                                                    unsigned long long b,
                                                    unsigned long long c) {
    unsigned long long d;
    asm("fma.rn.f32x2 %0, %1, %2, %3;" : "=l"(d) : "l"(a), "l"(b), "l"(c));
    return d;
}
__device__ __forceinline__ float f2_sum(unsigned long long v) {
    return __uint_as_float((unsigned)v) + __uint_as_float((unsigned)(v >> 32));
}

__device__ __forceinline__ void cpa16(const void* smem_dst, const void* gsrc) {
    unsigned a = (unsigned)__cvta_generic_to_shared(smem_dst);
    asm volatile("cp.async.cg.shared.global [%0], [%1], 16;" :: "r"(a), "l"(gsrc));
}
__device__ __forceinline__ void cpa_commit() {
    asm volatile("cp.async.commit_group;" ::: "memory");
}
__device__ __forceinline__ void cpa_wait0() {
    asm volatile("cp.async.wait_group 0;" ::: "memory");
}

// ---------------- kernel 1: router (4 tokens per block) ----------------
__global__ __launch_bounds__(256) void router_kernel(const float* __restrict__ x,
                                                     const float* __restrict__ rw) {
    __shared__ float xs[4 * DM];
    __shared__ float lg[4 * NE];
    int tid = threadIdx.x, lane = tid & 31, warp = tid >> 5;
    int tbase = blockIdx.x * 4;

    for (int i = tid; i < 4 * DM / 4; i += 256)
        *(float4*)(xs + i * 4) = *(const float4*)(x + (size_t)tbase * DM + i * 4);
    __syncthreads();

    for (int j = 0; j < 8; j++) {
        int e = warp * 8 + j;
        const float* w = rw + (size_t)e * DM;
        float acc[4] = {0.f, 0.f, 0.f, 0.f};
        #pragma unroll
        for (int q = 0; q < 4; q++) {
            float4 wv = *(const float4*)(w + (size_t)(lane + 32 * q) * 4);
            int kb = (lane + 32 * q) * 4;
            #pragma unroll
            for (int t = 0; t < 4; t++) {
                acc[t] += wv.x * xs[t * DM + kb + 0];
                acc[t] += wv.y * xs[t * DM + kb + 1];
                acc[t] += wv.z * xs[t * DM + kb + 2];
                acc[t] += wv.w * xs[t * DM + kb + 3];
            }
        }
        #pragma unroll
        for (int t = 0; t < 4; t++) {
            float a = acc[t];
            #pragma unroll
            for (int off = 16; off; off >>= 1) a += __shfl_xor_sync(0xffffffffu, a, off);
            if (lane == 0) lg[t * NE + e] = a;
        }
    }
    __syncthreads();

    if (warp < 4) {
        int tl = warp;
        int t = tbase + tl;
        float l0 = lg[tl * NE + lane];
        float l1 = lg[tl * NE + lane + 32];
        float m = fmaxf(l0, l1);
        #pragma unroll
        for (int off = 16; off; off >>= 1) m = fmaxf(m, __shfl_xor_sync(0xffffffffu, m, off));
        float p0 = expf(l0 - m), p1 = expf(l1 - m);
        float s = p0 + p1;
        #pragma unroll
        for (int off = 16; off; off >>= 1) s += __shfl_xor_sync(0xffffffffu, s, off);
        g_probs[(size_t)t * NE + lane]      = p0 / s;
        g_probs[(size_t)t * NE + lane + 32] = p1 / s;

        float v; int ix;
        if (l1 > l0) { v = l1; ix = lane + 32; } else { v = l0; ix = lane; }
        #pragma unroll
        for (int off = 16; off; off >>= 1) {
            float ov = __shfl_xor_sync(0xffffffffu, v, off);
            int   oi = __shfl_xor_sync(0xffffffffu, ix, off);
            if (ov > v || (ov == v && oi < ix)) { v = ov; ix = oi; }
        }
        float v1 = v; int i1 = ix;
        float c0 = (lane == i1)      ? -INFINITY : l0;
        float c1 = (lane + 32 == i1) ? -INFINITY : l1;
        if (c1 > c0) { v = c1; ix = lane + 32; } else { v = c0; ix = lane; }
        #pragma unroll
        for (int off = 16; off; off >>= 1) {
            float ov = __shfl_xor_sync(0xffffffffu, v, off);
            int   oi = __shfl_xor_sync(0xffffffffu, ix, off);
            if (ov > v || (ov == v && oi < ix)) { v = ov; ix = oi; }
        }
        float v2 = v; int i2 = ix;
        if (lane == 0) {
            float q = expf(v2 - v1);
            g_topidx[2 * t]     = i1;
            g_topidx[2 * t + 1] = i2;
            g_topw[2 * t]       = 1.f / (1.f + q);
            g_topw[2 * t + 1]   = q / (1.f + q);
        }
    }
}

// ---------------- kernel 2: deterministic grouping + chunk table (1 block) ----------------
__global__ __launch_bounds__(1024) void group_kernel() {
    __shared__ int cnt_s[NE], off_s[NE];
    int tid = threadIdx.x, lane = tid & 31, warp = tid >> 5;

    for (int e = warp; e < NE; e += 32) {
        int c = 0;
        for (int ch = 0; ch < NPAIR / 32; ch++) {
            int a = g_topidx[ch * 32 + lane];
            unsigned mask = __ballot_sync(0xffffffffu, a == e);
            c += __popc(mask);
        }
        if (lane == 0) cnt_s[e] = c;
    }
    __syncthreads();
    if (tid == 0) {
        int r = 0, nc = 0;
        for (int e = 0; e < NE; e++) {
            off_s[e] = r;
            int n = cnt_s[e];
            for (int t0 = 0; t0 < n; t0 += 16) {
                g_chunkE[nc] = e;
                g_chunkB[nc] = r + t0;
                g_chunkN[nc] = min(16, n - t0);
                nc++;
            }
            r += n;
        }
        g_nch = nc;
    }
    __syncthreads();
    for (int e = warp; e < NE; e += 32) {
        int pos = off_s[e];
        for (int ch = 0; ch < NPAIR / 32; ch++) {
            int idx = ch * 32 + lane;
            int a = g_topidx[idx];
            unsigned mask = __ballot_sync(0xffffffffu, a == e);
            if (a == e) {
                int r = pos + __popc(mask & ((1u << lane) - 1u));
                g_rowTok[r] = idx;
                g_rowW[r]   = g_topw[idx];
            }
            pos += __popc(mask);
        }
    }
    if (tid < NE) { g_cnt[tid] = cnt_s[tid]; g_off[tid] = off_s[tid]; }
}

// ---------------- kernel 3: aux loss ----------------
__global__ __launch_bounds__(1024) void aux_kernel(float* auxp) {
    __shared__ float part[1024];
    int tid = threadIdx.x;
    int e = tid & 63, c = tid >> 6;
    float s = 0.f;
    int t0 = c * 32;
    for (int t = t0; t < t0 + 32; t++) s += g_probs[(size_t)t * NE + e];
    part[tid] = s;
    __syncthreads();
    if (tid < NE) {
        float tot = 0.f;
        for (int j = 0; j < 16; j++) tot += part[e + j * 64];
        part[tid] = tot * (64.0f / 512.0f);
    }
    __syncthreads();
    if (tid == 0 && auxp) {
        float m = 0.f;
        for (int i = 0; i < NE; i++) m += part[i];
        m *= (1.0f / 64.0f);
        float v = 0.f;
        for (int i = 0; i < NE; i++) { float d = part[i] - m; v += d * d; }
        auxp[0] = v * (1.0f / 63.0f);
    }
}

// ---------------- kernel 4: gate/up grouped GEMM -> h = silu(g)*u ----------------
// grid (16 ftiles of 64, CHMAX chunks), 128 thr (4 warps).
// warp covers 16 f rows; lane: t8 = lane&7 (tokens t8, t8+8), fh = lane>>3;
// thread f rows = warp*16 + fh + 4j (j<4), both matrices.
// Register tile 2 tok x 4 f x 2 mats = 16 f32x2 accums.
#define GU_KC 16
#define GU_ST (DM / GU_KC)   // 32 stages
__global__ __launch_bounds__(128, 5) void gateup_kernel(const float* __restrict__ x,
                                                        const float* __restrict__ wg,
                                                        const float* __restrict__ wu) {
    int c = blockIdx.y;
    if (c >= g_nch) return;
    int e     = g_chunkE[c];
    int rbase = g_chunkB[c];
    int cnt   = g_chunkN[c];
    int ft = blockIdx.x * 64;

    __shared__ __align__(16) float xs[2][16][20];
    __shared__ __align__(16) float ws[2][2][64][20];
    __shared__ int tok_s[16];

    int tid = threadIdx.x, lane = tid & 31, warp = tid >> 5;
    int t8 = lane & 7, fh = lane >> 3;
    int fbase = warp * 16 + fh;

    const float* wmat0 = wg + ((size_t)e * DE + ft) * DM;
    const float* wmat1 = wu + ((size_t)e * DE + ft) * DM;

    if (tid < 16) {
        int rr = min(tid, cnt - 1);
        tok_s[tid] = g_rowTok[rbase + rr] >> 1;
    }
    __syncthreads();

    // per-thread fixed load assignment: weights 4x float4, x 1x float4 (tid<64)
    int wp_mat[4], wp_r[4], wp_c[4];
    #pragma unroll
    for (int i = 0; i < 4; i++) {
        int p = i * 128 + tid;
        wp_mat[i] = p >> 8;
        int pm = p & 255;
        wp_r[i] = pm >> 2;
        wp_c[i] = (pm & 3) * 4;
    }
    int xr_ = tid >> 2, xc_ = (tid & 3) * 4;
    const float* myX = (tid < 64) ? (x + (size_t)tok_s[xr_] * DM + xc_) : x;

    unsigned long long ag[2][4], au[2][4];
    #pragma unroll
    for (int s = 0; s < 2; s++)
        #pragma unroll
        for (int j = 0; j < 4; j++) { ag[s][j] = 0ull; au[s][j] = 0ull; }

    auto loadStage = [&](int s, int bb) {
        int k0 = s * GU_KC;
        #pragma unroll
        for (int i = 0; i < 4; i++) {
            const float* src = (wp_mat[i] ? wmat1 : wmat0) + (size_t)wp_r[i] * DM + k0 + wp_c[i];
            cpa16(&ws[bb][wp_mat[i]][wp_r[i]][wp_c[i]], src);
        }
        if (tid < 64) cpa16(&xs[bb][xr_][xc_], myX + k0);
        cpa_commit();
    };

    loadStage(0, 0);
    for (int s = 0; s < GU_ST; s++) {
        cpa_wait0();
        __syncthreads();
        if (s + 1 < GU_ST) loadStage(s + 1, (s + 1) & 1);
        int bb = s & 1;
        #pragma unroll
        for (int q = 0; q < 4; q++) {
            ulonglong2 xA = *(const ulonglong2*)&xs[bb][t8][4 * q];
            ulonglong2 xB = *(const ulonglong2*)&xs[bb][t8 + 8][4 * q];
            #pragma unroll
            for (int j = 0; j < 4; j++) {
                ulonglong2 wg2 = *(const ulonglong2*)&ws[bb][0][fbase + 4 * j][4 * q];
                ag[0][j] = ffma2(wg2.x, xA.x, ag[0][j]);
                ag[0][j] = ffma2(wg2.y, xA.y, ag[0][j]);
                ag[1][j] = ffma2(wg2.x, xB.x, ag[1][j]);
                ag[1][j] = ffma2(wg2.y, xB.y, ag[1][j]);
                ulonglong2 wu2 = *(const ulonglong2*)&ws[bb][1][fbase + 4 * j][4 * q];
                au[0][j] = ffma2(wu2.x, xA.x, au[0][j]);
                au[0][j] = ffma2(wu2.y, xA.y, au[0][j]);
                au[1][j] = ffma2(wu2.x, xB.x, au[1][j]);
                au[1][j] = ffma2(wu2.y, xB.y, au[1][j]);
            }
        }
    }

    #pragma unroll
    for (int s = 0; s < 2; s++) {
        int tt = t8 + 8 * s;
        if (tt < cnt) {
            int row = rbase + tt;
            float* hp = g_h + (size_t)row * DE + ft + fbase;
            #pragma unroll
            for (int j = 0; j < 4; j++) {
                float g = f2_sum(ag[s][j]);
                float u = f2_sum(au[s][j]);
                hp[4 * j] = (g / (1.f + expf(-g))) * u;
            }
        }
    }
}

// ---------------- kernel 5: down grouped GEMM + weighted scatter ----------------
// grid (4 dtiles of 128, CHMAX chunks), 128 thr (4 warps).
// warp covers 32 d rows; thread d rows = warp*32 + fh + 4j (j<8); 2 tok x 8 d accums.
#define DN_KC 32
#define DN_ST (DE / DN_KC)   // 32 stages
__global__ __launch_bounds__(128, 5) void down_kernel(const float* __restrict__ wd,
                                                      float* __restrict__ out) {
    int c = blockIdx.y;
    if (c >= g_nch) return;
    int e     = g_chunkE[c];
    int rbase = g_chunkB[c];
    int cnt   = g_chunkN[c];
    int dt = blockIdx.x * 128;

    __shared__ __align__(16) float hs[2][16][36];
    __shared__ __align__(16) float ws2[2][128][36];
    __shared__ int row_s[16];

    int tid = threadIdx.x, lane = tid & 31, warp = tid >> 5;
    int t8 = lane & 7, fh = lane >> 3;
    int dbase = warp * 32 + fh;

    const float* wdE = wd + ((size_t)e * DM + dt) * DE;

    if (tid < 16) {
        int rr = min(tid, cnt - 1);
        row_s[tid] = rbase + rr;
    }
    __syncthreads();

    int wp_r[8], wp_c[8];
    #pragma unroll
    for (int i = 0; i < 8; i++) {
        int p = i * 128 + tid;
        wp_r[i] = p >> 3;
        wp_c[i] = (p & 7) * 4;
    }
    int hr_ = tid >> 3, hc_ = (tid & 7) * 4;
    const float* myH = g_h + (size_t)row_s[hr_] * DE + hc_;

    unsigned long long acc[2][8];
    #pragma unroll
    for (int s = 0; s < 2; s++)
        #pragma unroll
        for (int j = 0; j < 8; j++) acc[s][j] = 0ull;

    auto loadStage = [&](int s, int bb) {
        int k0 = s * DN_KC;
        #pragma unroll
        for (int i = 0; i < 8; i++)
            cpa16(&ws2[bb][wp_r[i]][wp_c[i]], wdE + (size_t)wp_r[i] * DE + k0 + wp_c[i]);
        cpa16(&hs[bb][hr_][hc_], myH + k0);
        cpa_commit();
    };

    loadStage(0, 0);
    for (int s = 0; s < DN_ST; s++) {
        cpa_wait0();
        __syncthreads();
        if (s + 1 < DN_ST) loadStage(s + 1, (s + 1) & 1);
        int bb = s & 1;
        #pragma unroll
        for (int q = 0; q < 8; q++) {
            ulonglong2 hA = *(const ulonglong2*)&hs[bb][t8][4 * q];
            ulonglong2 hB = *(const ulonglong2*)&hs[bb][t8 + 8][4 * q];
            #pragma unroll
            for (int j = 0; j < 8; j++) {
                ulonglong2 w2 = *(const ulonglong2*)&ws2[bb][dbase + 4 * j][4 * q];
                acc[0][j] = ffma2(w2.x, hA.x, acc[0][j]);
                acc[0][j] = ffma2(w2.y, hA.y, acc[0][j]);
                acc[1][j] = ffma2(w2.x, hB.x, acc[1][j]);
                acc[1][j] = ffma2(w2.y, hB.y, acc[1][j]);
            }
        }
    }

    #pragma unroll
    for (int s = 0; s < 2; s++) {
        int tt = t8 + 8 * s;
        if (tt < cnt) {
            int fidx = g_rowTok[rbase + tt];
            int tok = fidx >> 1;
            float wt = g_rowW[rbase + tt];
            float* op = out + (size_t)tok * DM + dt + dbase;
            #pragma unroll
            for (int j = 0; j < 8; j++)
                atomicAdd(op + 4 * j, wt * f2_sum(acc[s][j]));
        }
    }
}

// ---------------- launch ----------------
extern "C" void kernel_launch(void* const* d_in, const int* in_sizes, int n_in,
                              void* d_out, int out_size) {
    const float* x  = (const float*)d_in[0];
    const float* rw = (const float*)d_in[1];
    const float* wg = (const float*)d_in[2];
    const float* wu = (const float*)d_in[3];
    const float* wd = (const float*)d_in[4];
    float* out = (float*)d_out;

    cudaMemsetAsync(d_out, 0, (size_t)out_size * sizeof(float), 0);

    router_kernel<<<T_TOK / 4, 256>>>(x, rw);
    group_kernel<<<1, 1024>>>();

    float* auxp = (out_size > T_TOK * DM) ? out + (size_t)T_TOK * DM : nullptr;
    aux_kernel<<<1, 1024>>>(auxp);

    gateup_kernel<<<dim3(16, CHMAX), 128>>>(x, wg, wu);
    down_kernel<<<dim3(4, CHMAX), 128>>>(wd, out);
}

// round 5
// speedup vs baseline: 2.2339x; 1.0693x over previous
#include <cuda_runtime.h>
#include <math.h>

#define T_TOK 512
#define DM    512
#define DE    1024
#define NE    64
#define NPAIR 1024
#define CHMAX 128

// ---------------- scratch (static device globals; no allocation) ----------------
__device__ float g_probs[T_TOK * NE];
__device__ int   g_topidx[NPAIR];
__device__ float g_topw[NPAIR];
__device__ int   g_rowTok[NPAIR];
__device__ float g_rowW[NPAIR];
__device__ int   g_cnt[NE];
__device__ int   g_off[NE];
__device__ int   g_chunkE[CHMAX], g_chunkB[CHMAX], g_chunkN[CHMAX];
__device__ int   g_nch;
__device__ float g_h[(size_t)NPAIR * DE];   // silu(gate)*up, [row][F], 4 MB

// ---------------- packed f32x2 FMA ----------------
__device__ __forceinline__ unsigned long long ffma2(unsigned long long a,
                                                    unsigned long long b,
                                                    unsigned long long c) {
    unsigned long long d;
    asm("fma.rn.f32x2 %0, %1, %2, %3;" : "=l"(d) : "l"(a), "l"(b), "l"(c));
    return d;
}
__device__ __forceinline__ float f2_sum(unsigned long long v) {
    return __uint_as_float((unsigned)v) + __uint_as_float((unsigned)(v >> 32));
}

__device__ __forceinline__ void cpa16(const void* smem_dst, const void* gsrc) {
    unsigned a = (unsigned)__cvta_generic_to_shared(smem_dst);
    asm volatile("cp.async.cg.shared.global [%0], [%1], 16;" :: "r"(a), "l"(gsrc));
}
__device__ __forceinline__ void cpa_commit() {
    asm volatile("cp.async.commit_group;" ::: "memory");
}
__device__ __forceinline__ void cpa_wait0() {
    asm volatile("cp.async.wait_group 0;" ::: "memory");
}

// ---------------- kernel 1: router (4 tokens per block) ----------------
__global__ __launch_bounds__(256) void router_kernel(const float* __restrict__ x,
                                                     const float* __restrict__ rw) {
    __shared__ float xs[4 * DM];
    __shared__ float lg[4 * NE];
    int tid = threadIdx.x, lane = tid & 31, warp = tid >> 5;
    int tbase = blockIdx.x * 4;

    for (int i = tid; i < 4 * DM / 4; i += 256)
        *(float4*)(xs + i * 4) = *(const float4*)(x + (size_t)tbase * DM + i * 4);
    __syncthreads();

    for (int j = 0; j < 8; j++) {
        int e = warp * 8 + j;
        const float* w = rw + (size_t)e * DM;
        float acc[4] = {0.f, 0.f, 0.f, 0.f};
        #pragma unroll
        for (int q = 0; q < 4; q++) {
            float4 wv = *(const float4*)(w + (size_t)(lane + 32 * q) * 4);
            int kb = (lane + 32 * q) * 4;
            #pragma unroll
            for (int t = 0; t < 4; t++) {
                acc[t] += wv.x * xs[t * DM + kb + 0];
                acc[t] += wv.y * xs[t * DM + kb + 1];
                acc[t] += wv.z * xs[t * DM + kb + 2];
                acc[t] += wv.w * xs[t * DM + kb + 3];
            }
        }
        #pragma unroll
        for (int t = 0; t < 4; t++) {
            float a = acc[t];
            #pragma unroll
            for (int off = 16; off; off >>= 1) a += __shfl_xor_sync(0xffffffffu, a, off);
            if (lane == 0) lg[t * NE + e] = a;
        }
    }
    __syncthreads();

    if (warp < 4) {
        int tl = warp;
        int t = tbase + tl;
        float l0 = lg[tl * NE + lane];
        float l1 = lg[tl * NE + lane + 32];
        float m = fmaxf(l0, l1);
        #pragma unroll
        for (int off = 16; off; off >>= 1) m = fmaxf(m, __shfl_xor_sync(0xffffffffu, m, off));
        float p0 = expf(l0 - m), p1 = expf(l1 - m);
        float s = p0 + p1;
        #pragma unroll
        for (int off = 16; off; off >>= 1) s += __shfl_xor_sync(0xffffffffu, s, off);
        g_probs[(size_t)t * NE + lane]      = p0 / s;
        g_probs[(size_t)t * NE + lane + 32] = p1 / s;

        float v; int ix;
        if (l1 > l0) { v = l1; ix = lane + 32; } else { v = l0; ix = lane; }
        #pragma unroll
        for (int off = 16; off; off >>= 1) {
            float ov = __shfl_xor_sync(0xffffffffu, v, off);
            int   oi = __shfl_xor_sync(0xffffffffu, ix, off);
            if (ov > v || (ov == v && oi < ix)) { v = ov; ix = oi; }
        }
        float v1 = v; int i1 = ix;
        float c0 = (lane == i1)      ? -INFINITY : l0;
        float c1 = (lane + 32 == i1) ? -INFINITY : l1;
        if (c1 > c0) { v = c1; ix = lane + 32; } else { v = c0; ix = lane; }
        #pragma unroll
        for (int off = 16; off; off >>= 1) {
            float ov = __shfl_xor_sync(0xffffffffu, v, off);
            int   oi = __shfl_xor_sync(0xffffffffu, ix, off);
            if (ov > v || (ov == v && oi < ix)) { v = ov; ix = oi; }
        }
        float v2 = v; int i2 = ix;
        if (lane == 0) {
            float q = expf(v2 - v1);
            g_topidx[2 * t]     = i1;
            g_topidx[2 * t + 1] = i2;
            g_topw[2 * t]       = 1.f / (1.f + q);
            g_topw[2 * t + 1]   = q / (1.f + q);
        }
    }
}

// ---------------- kernel 2: deterministic grouping + chunk table (1 block) ----------------
__global__ __launch_bounds__(1024) void group_kernel() {
    __shared__ int cnt_s[NE], off_s[NE];
    int tid = threadIdx.x, lane = tid & 31, warp = tid >> 5;

    for (int e = warp; e < NE; e += 32) {
        int c = 0;
        for (int ch = 0; ch < NPAIR / 32; ch++) {
            int a = g_topidx[ch * 32 + lane];
            unsigned mask = __ballot_sync(0xffffffffu, a == e);
            c += __popc(mask);
        }
        if (lane == 0) cnt_s[e] = c;
    }
    __syncthreads();
    if (tid == 0) {
        int r = 0, nc = 0;
        for (int e = 0; e < NE; e++) {
            off_s[e] = r;
            int n = cnt_s[e];
            for (int t0 = 0; t0 < n; t0 += 16) {
                g_chunkE[nc] = e;
                g_chunkB[nc] = r + t0;
                g_chunkN[nc] = min(16, n - t0);
                nc++;
            }
            r += n;
        }
        g_nch = nc;
    }
    __syncthreads();
    for (int e = warp; e < NE; e += 32) {
        int pos = off_s[e];
        for (int ch = 0; ch < NPAIR / 32; ch++) {
            int idx = ch * 32 + lane;
            int a = g_topidx[idx];
            unsigned mask = __ballot_sync(0xffffffffu, a == e);
            if (a == e) {
                int r = pos + __popc(mask & ((1u << lane) - 1u));
                g_rowTok[r] = idx;
                g_rowW[r]   = g_topw[idx];
            }
            pos += __popc(mask);
        }
    }
    if (tid < NE) { g_cnt[tid] = cnt_s[tid]; g_off[tid] = off_s[tid]; }
}

// ---------------- kernel 3: aux loss ----------------
__global__ __launch_bounds__(1024) void aux_kernel(float* auxp) {
    __shared__ float part[1024];
    int tid = threadIdx.x;
    int e = tid & 63, c = tid >> 6;
    float s = 0.f;
    int t0 = c * 32;
    for (int t = t0; t < t0 + 32; t++) s += g_probs[(size_t)t * NE + e];
    part[tid] = s;
    __syncthreads();
    if (tid < NE) {
        float tot = 0.f;
        for (int j = 0; j < 16; j++) tot += part[e + j * 64];
        part[tid] = tot * (64.0f / 512.0f);
    }
    __syncthreads();
    if (tid == 0 && auxp) {
        float m = 0.f;
        for (int i = 0; i < NE; i++) m += part[i];
        m *= (1.0f / 64.0f);
        float v = 0.f;
        for (int i = 0; i < NE; i++) { float d = part[i] - m; v += d * d; }
        auxp[0] = v * (1.0f / 63.0f);
    }
}

// ---------------- kernel 4: gate/up grouped GEMM -> h = silu(g)*u ----------------
// grid (8 ftiles of 128, CHMAX chunks), 128 thr (4 warps).
// lane: t4 = lane&3 (tokens t4+4i, i<4), fh = lane>>2 (0..7).
// thread f rows = warp*32 + fh + 8j (j<4), both matrices.
// Register tile: 4 tok x (4 gate + 4 up) = 32 f32x2 accums (64 regs).
#define GU_KC 16
#define GU_ST (DM / GU_KC)   // 32 stages
__global__ __launch_bounds__(128, 4) void gateup_kernel(const float* __restrict__ x,
                                                        const float* __restrict__ wg,
                                                        const float* __restrict__ wu) {
    int c = blockIdx.y;
    if (c >= g_nch) return;
    int e     = g_chunkE[c];
    int rbase = g_chunkB[c];
    int cnt   = g_chunkN[c];
    int ft = blockIdx.x * 128;

    __shared__ __align__(16) float xs[2][16][20];
    __shared__ __align__(16) float ws[2][2][128][20];
    __shared__ int tok_s[16];

    int tid = threadIdx.x, lane = tid & 31, warp = tid >> 5;
    int t4 = lane & 3, fh = lane >> 2;
    int fbase = warp * 32 + fh;

    const float* wmat0 = wg + ((size_t)e * DE + ft) * DM;
    const float* wmat1 = wu + ((size_t)e * DE + ft) * DM;

    if (tid < 16) {
        int rr = min(tid, cnt - 1);
        tok_s[tid] = g_rowTok[rbase + rr] >> 1;
    }
    __syncthreads();

    // weight load assignment: 8x float4 per thread over [2][128][4 float4]
    int wp_mat[8], wp_r[8], wp_c[8];
    #pragma unroll
    for (int i = 0; i < 8; i++) {
        int p = i * 128 + tid;
        wp_mat[i] = p >> 9;
        int pm = p & 511;
        wp_r[i] = pm >> 2;
        wp_c[i] = (pm & 3) * 4;
    }
    int xr_ = tid >> 2, xc_ = (tid & 3) * 4;
    const float* myX = (tid < 64) ? (x + (size_t)tok_s[xr_] * DM + xc_) : x;

    unsigned long long ag[4][4], au[4][4];
    #pragma unroll
    for (int i = 0; i < 4; i++)
        #pragma unroll
        for (int j = 0; j < 4; j++) { ag[i][j] = 0ull; au[i][j] = 0ull; }

    auto loadStage = [&](int s, int bb) {
        int k0 = s * GU_KC;
        #pragma unroll
        for (int i = 0; i < 8; i++) {
            const float* src = (wp_mat[i] ? wmat1 : wmat0) + (size_t)wp_r[i] * DM + k0 + wp_c[i];
            cpa16(&ws[bb][wp_mat[i]][wp_r[i]][wp_c[i]], src);
        }
        if (tid < 64) cpa16(&xs[bb][xr_][xc_], myX + k0);
        cpa_commit();
    };

    loadStage(0, 0);
    for (int s = 0; s < GU_ST; s++) {
        cpa_wait0();
        __syncthreads();
        if (s + 1 < GU_ST) loadStage(s + 1, (s + 1) & 1);
        int bb = s & 1;
        #pragma unroll
        for (int q = 0; q < 4; q++) {
            ulonglong2 xv[4];
            #pragma unroll
            for (int i = 0; i < 4; i++)
                xv[i] = *(const ulonglong2*)&xs[bb][t4 + 4 * i][4 * q];
            #pragma unroll
            for (int j = 0; j < 4; j++) {
                ulonglong2 wgv = *(const ulonglong2*)&ws[bb][0][fbase + 8 * j][4 * q];
                ulonglong2 wuv = *(const ulonglong2*)&ws[bb][1][fbase + 8 * j][4 * q];
                #pragma unroll
                for (int i = 0; i < 4; i++) {
                    ag[i][j] = ffma2(wgv.x, xv[i].x, ag[i][j]);
                    ag[i][j] = ffma2(wgv.y, xv[i].y, ag[i][j]);
                    au[i][j] = ffma2(wuv.x, xv[i].x, au[i][j]);
                    au[i][j] = ffma2(wuv.y, xv[i].y, au[i][j]);
                }
            }
        }
    }

    #pragma unroll
    for (int i = 0; i < 4; i++) {
        int tt = t4 + 4 * i;
        if (tt < cnt) {
            int row = rbase + tt;
            float* hp = g_h + (size_t)row * DE + ft + fbase;
            #pragma unroll
            for (int j = 0; j < 4; j++) {
                float g = f2_sum(ag[i][j]);
                float u = f2_sum(au[i][j]);
                hp[8 * j] = (g / (1.f + expf(-g))) * u;
            }
        }
    }
}

// ---------------- kernel 5: down grouped GEMM + weighted scatter ----------------
// grid (4 dtiles of 128, CHMAX chunks), 128 thr, KC=32.
// lane: t4 = lane&3, fh = lane>>2 (0..7).
// thread d rows = warp*32 + fh + 8j (j<4)  -> exactly 128 rows per block.
// Register tile: 4 tok x 4 d = 16 f32x2 accums.
#define DN_KC 32
#define DN_ST (DE / DN_KC)   // 32 stages
__global__ __launch_bounds__(128, 4) void down_kernel(const float* __restrict__ wd,
                                                      float* __restrict__ out) {
    int c = blockIdx.y;
    if (c >= g_nch) return;
    int e     = g_chunkE[c];
    int rbase = g_chunkB[c];
    int cnt   = g_chunkN[c];
    int dt = blockIdx.x * 128;

    __shared__ __align__(16) float hs[2][16][36];
    __shared__ __align__(16) float ws2[2][128][36];
    __shared__ int row_s[16];

    int tid = threadIdx.x, lane = tid & 31, warp = tid >> 5;
    int t4 = lane & 3, fh = lane >> 2;
    int dbase = warp * 32 + fh;

    const float* wdE = wd + ((size_t)e * DM + dt) * DE;

    if (tid < 16) {
        int rr = min(tid, cnt - 1);
        row_s[tid] = rbase + rr;
    }
    __syncthreads();

    int wp_r[8], wp_c[8];
    #pragma unroll
    for (int i = 0; i < 8; i++) {
        int p = i * 128 + tid;
        wp_r[i] = p >> 3;
        wp_c[i] = (p & 7) * 4;
    }
    int hr_ = tid >> 3, hc_ = (tid & 7) * 4;
    const float* myH = g_h + (size_t)row_s[hr_] * DE + hc_;

    unsigned long long acc[4][4];
    #pragma unroll
    for (int i = 0; i < 4; i++)
        #pragma unroll
        for (int j = 0; j < 4; j++) acc[i][j] = 0ull;

    auto loadStage = [&](int s, int bb) {
        int k0 = s * DN_KC;
        #pragma unroll
        for (int i = 0; i < 8; i++)
            cpa16(&ws2[bb][wp_r[i]][wp_c[i]], wdE + (size_t)wp_r[i] * DE + k0 + wp_c[i]);
        cpa16(&hs[bb][hr_][hc_], myH + k0);
        cpa_commit();
    };

    loadStage(0, 0);
    for (int s = 0; s < DN_ST; s++) {
        cpa_wait0();
        __syncthreads();
        if (s + 1 < DN_ST) loadStage(s + 1, (s + 1) & 1);
        int bb = s & 1;
        #pragma unroll
        for (int q = 0; q < 8; q++) {
            ulonglong2 hv[4];
            #pragma unroll
            for (int i = 0; i < 4; i++)
                hv[i] = *(const ulonglong2*)&hs[bb][t4 + 4 * i][4 * q];
            #pragma unroll
            for (int j = 0; j < 4; j++) {
                ulonglong2 wv = *(const ulonglong2*)&ws2[bb][dbase + 8 * j][4 * q];
                #pragma unroll
                for (int i = 0; i < 4; i++) {
                    acc[i][j] = ffma2(wv.x, hv[i].x, acc[i][j]);
                    acc[i][j] = ffma2(wv.y, hv[i].y, acc[i][j]);
                }
            }
        }
    }

    #pragma unroll
    for (int i = 0; i < 4; i++) {
        int tt = t4 + 4 * i;
        if (tt < cnt) {
            int fidx = g_rowTok[rbase + tt];
            int tok = fidx >> 1;
            float wt = g_rowW[rbase + tt];
            float* op = out + (size_t)tok * DM + dt + dbase;
            #pragma unroll
            for (int j = 0; j < 4; j++)
                atomicAdd(op + 8 * j, wt * f2_sum(acc[i][j]));
        }
    }
}

// ---------------- launch ----------------
extern "C" void kernel_launch(void* const* d_in, const int* in_sizes, int n_in,
                              void* d_out, int out_size) {
    const float* x  = (const float*)d_in[0];
    const float* rw = (const float*)d_in[1];
    const float* wg = (const float*)d_in[2];
    const float* wu = (const float*)d_in[3];
    const float* wd = (const float*)d_in[4];
    float* out = (float*)d_out;

    cudaMemsetAsync(d_out, 0, (size_t)out_size * sizeof(float), 0);

    router_kernel<<<T_TOK / 4, 256>>>(x, rw);
    group_kernel<<<1, 1024>>>();

    float* auxp = (out_size > T_TOK * DM) ? out + (size_t)T_TOK * DM : nullptr;
    aux_kernel<<<1, 1024>>>(auxp);

    gateup_kernel<<<dim3(8, CHMAX), 128>>>(x, wg, wu);
    down_kernel<<<dim3(4, CHMAX), 128>>>(wd, out);
}